// round 10
// baseline (speedup 1.0000x reference)
#include <cuda_runtime.h>
#include <cuda_bf16.h>
#include <cstdint>
#include <cstddef>

#define BB 256
#define TT 512
#define II 128
#define HH 256
#define GG 768

typedef unsigned long long u64;

__device__ float g_xg[(size_t)BB * TT * GG];

// ---------------- bf16 helpers ----------------
__device__ __forceinline__ uint32_t pkbf(float x, float y) {
    __nv_bfloat162 h = __floats2bfloat162_rn(x, y);
    return *(uint32_t*)&h;
}
__device__ __forceinline__ float bfres(float x) {   // x - bf16(x)
    return x - __bfloat162float(__float2bfloat16(x));
}
__device__ __forceinline__ void ldsm_x4(uint32_t& r0, uint32_t& r1,
                                        uint32_t& r2, uint32_t& r3, uint32_t a) {
    asm volatile("ldmatrix.sync.aligned.m8n8.x4.shared.b16 {%0,%1,%2,%3}, [%4];"
                 : "=r"(r0), "=r"(r1), "=r"(r2), "=r"(r3) : "r"(a));
}
__device__ __forceinline__ void ldsm_x4t(uint32_t& r0, uint32_t& r1,
                                         uint32_t& r2, uint32_t& r3, uint32_t a) {
    asm volatile("ldmatrix.sync.aligned.m8n8.x4.trans.shared.b16 {%0,%1,%2,%3}, [%4];"
                 : "=r"(r0), "=r"(r1), "=r"(r2), "=r"(r3) : "r"(a));
}
__device__ __forceinline__ void mma16816(float& c0, float& c1, float& c2, float& c3,
                                         uint32_t a0, uint32_t a1, uint32_t a2, uint32_t a3,
                                         uint32_t b0, uint32_t b1) {
    asm("mma.sync.aligned.m16n8k16.row.col.f32.bf16.bf16.f32 "
        "{%0,%1,%2,%3}, {%4,%5,%6,%7}, {%8,%9}, {%0,%1,%2,%3};"
        : "+f"(c0), "+f"(c1), "+f"(c2), "+f"(c3)
        : "r"(a0), "r"(a1), "r"(a2), "r"(a3), "r"(b0), "r"(b1));
}

// ---------------------------------------------------------------------------
// Phase 1 (R9 frozen, ~284us): xg = x @ W_ih^T + b_ih, HMMA bf16-split.
// ---------------------------------------------------------------------------
#define SM1_AHI 0
#define SM1_ALO 32768
#define SM1_BHI 65536
#define SM1_BLO 81920
#define SM1_BYTES 98304

__global__ __launch_bounds__(256, 2) void xg_mma_kernel(
    const float* __restrict__ x,
    const float* __restrict__ Wih,
    const float* __restrict__ bih)
{
    extern __shared__ char sm1[];
    const uint32_t smb = (uint32_t)__cvta_generic_to_shared(sm1);
    const int tid  = threadIdx.x;
    const int warp = tid >> 5;
    const int lane = tid & 31;
    const int bn = blockIdx.x;
    const int bm = blockIdx.y;

    {
        const float* xr = x + (size_t)bm * 128 * II;
        const int r_ = tid >> 5, kq = tid & 31;
        const uint32_t off0 = (uint32_t)((((kq >> 1) ^ (r_ & 7)) << 4) + (kq & 1) * 8);
#pragma unroll
        for (int i = 0; i < 16; ++i) {
            int r = r_ + i * 8;
            float4 v = *(const float4*)(xr + (size_t)r * II + kq * 4);
            uint2 hi = make_uint2(pkbf(v.x, v.y), pkbf(v.z, v.w));
            uint2 lo = make_uint2(pkbf(bfres(v.x), bfres(v.y)),
                                  pkbf(bfres(v.z), bfres(v.w)));
            uint32_t off = (uint32_t)(r * 256) + off0;
            *(uint2*)(sm1 + SM1_AHI + off) = hi;
            *(uint2*)(sm1 + SM1_ALO + off) = lo;
        }
        const float* wr = Wih + (size_t)bn * 64 * II;
#pragma unroll
        for (int i = 0; i < 8; ++i) {
            int n = r_ + i * 8;
            float4 v = *(const float4*)(wr + (size_t)n * II + kq * 4);
            uint2 hi = make_uint2(pkbf(v.x, v.y), pkbf(v.z, v.w));
            uint2 lo = make_uint2(pkbf(bfres(v.x), bfres(v.y)),
                                  pkbf(bfres(v.z), bfres(v.w)));
            uint32_t off = (uint32_t)(n * 256) + off0;
            *(uint2*)(sm1 + SM1_BHI + off) = hi;
            *(uint2*)(sm1 + SM1_BLO + off) = lo;
        }
    }
    __syncthreads();

    const int mr2 = warp >> 1;
    const int nc2 = warp & 1;
    const uint32_t lrow  = (uint32_t)(lane & 15);
    const uint32_t khalf = (uint32_t)(lane >> 4);
    const uint32_t r7    = lrow & 7u;
    const uint32_t aRB = smb + SM1_AHI + (uint32_t)(mr2 * 32 + lrow) * 256u;
    const uint32_t bRB = smb + SM1_BHI + (uint32_t)(nc2 * 32 + lrow) * 256u;

    float c[2][4][4];
#pragma unroll
    for (int m = 0; m < 2; ++m)
#pragma unroll
        for (int n = 0; n < 4; ++n)
#pragma unroll
            for (int q = 0; q < 4; ++q) c[m][n][q] = 0.f;

#pragma unroll
    for (int kt = 0; kt < 8; ++kt) {
        const uint32_t swz = (((uint32_t)(kt * 2) + khalf) ^ r7) << 4;
        uint32_t ah[2][4], al[2][4], bh[2][4], bl[2][4];
#pragma unroll
        for (int m = 0; m < 2; ++m) {
            uint32_t a = aRB + (uint32_t)(m * 4096) + swz;
            ldsm_x4(ah[m][0], ah[m][1], ah[m][2], ah[m][3], a);
            ldsm_x4(al[m][0], al[m][1], al[m][2], al[m][3], a + 32768u);
        }
#pragma unroll
        for (int nn = 0; nn < 2; ++nn) {
            uint32_t b = bRB + (uint32_t)(nn * 4096) + swz;
            ldsm_x4(bh[nn][0], bh[nn][1], bh[nn][2], bh[nn][3], b);
            ldsm_x4(bl[nn][0], bl[nn][1], bl[nn][2], bl[nn][3], b + 16384u);
        }
#pragma unroll
        for (int m = 0; m < 2; ++m) {
#pragma unroll
            for (int nn = 0; nn < 2; ++nn) {
                float* c0 = c[m][nn * 2];
                float* c1 = c[m][nn * 2 + 1];
                mma16816(c0[0], c0[1], c0[2], c0[3],
                         ah[m][0], ah[m][1], ah[m][2], ah[m][3],
                         bh[nn][0], bh[nn][2]);
                mma16816(c1[0], c1[1], c1[2], c1[3],
                         ah[m][0], ah[m][1], ah[m][2], ah[m][3],
                         bh[nn][1], bh[nn][3]);
                mma16816(c0[0], c0[1], c0[2], c0[3],
                         ah[m][0], ah[m][1], ah[m][2], ah[m][3],
                         bl[nn][0], bl[nn][2]);
                mma16816(c1[0], c1[1], c1[2], c1[3],
                         ah[m][0], ah[m][1], ah[m][2], ah[m][3],
                         bl[nn][1], bl[nn][3]);
                mma16816(c0[0], c0[1], c0[2], c0[3],
                         al[m][0], al[m][1], al[m][2], al[m][3],
                         bh[nn][0], bh[nn][2]);
                mma16816(c1[0], c1[1], c1[2], c1[3],
                         al[m][0], al[m][1], al[m][2], al[m][3],
                         bh[nn][1], bh[nn][3]);
            }
        }
    }

    const int gq = lane >> 2, tq = lane & 3;
#pragma unroll
    for (int nf = 0; nf < 4; ++nf) {
        int col = bn * 64 + nc2 * 32 + nf * 8 + tq * 2;
        float2 bb = *(const float2*)(bih + col);
#pragma unroll
        for (int m = 0; m < 2; ++m) {
            int row = bm * 128 + mr2 * 32 + m * 16 + gq;
            float2 o0 = make_float2(c[m][nf][0] + bb.x, c[m][nf][1] + bb.y);
            float2 o1 = make_float2(c[m][nf][2] + bb.x, c[m][nf][3] + bb.y);
            *(float2*)(g_xg + (size_t)row * GG + col) = o0;
            *(float2*)(g_xg + (size_t)(row + 8) * GG + col) = o1;
        }
    }
}

// ---------------------------------------------------------------------------
// Phase 2: HMMA recurrence, 6 independent accumulator chains, W1+W2 in SMEM,
// ldmatrix.x4.trans for hi+lo, mbarrier cluster signaling (no barrier.cluster
// in the loop), h_old in registers.
// ---------------------------------------------------------------------------
#define TPB2 384

#define OFF_W1   0                        // 12*16*512 = 98304
#define OFF_W2   98304                    // 98304
#define OFF_HSM  196608                   // 2*256*32 = 16384
#define OFF_PS   212992                   // 192*8*4  = 6144
#define OFF_BSM  219136                   // 768
#define OFF_MBAR 219904                   // 8
#define SM2_BYTES 219968

__device__ __forceinline__ void mbar_waitc(uint32_t mbar, uint32_t parity) {
    uint32_t done;
    asm volatile(
        "{\n\t.reg .pred p;\n\t"
        "mbarrier.try_wait.parity.acquire.cluster.shared::cta.b64 p, [%1], %2;\n\t"
        "selp.b32 %0, 1, 0, p;\n\t}"
        : "=r"(done) : "r"(mbar), "r"(parity) : "memory");
    if (!done) {
        asm volatile(
            "{\n\t.reg .pred P1;\n\t"
            "W%=:\n\t"
            "mbarrier.try_wait.parity.acquire.cluster.shared::cta.b64 P1, [%0], %1, 0x989680;\n\t"
            "@P1 bra.uni D%=;\n\t"
            "bra.uni W%=;\n\t"
            "D%=:\n\t}"
            :: "r"(mbar), "r"(parity) : "memory");
    }
}

__global__ __launch_bounds__(TPB2, 1) __cluster_dims__(4, 1, 1)
void gru_seq_mma(const float* __restrict__ Whh,
                 const float* __restrict__ bhh,
                 float* __restrict__ out)
{
    extern __shared__ char smem[];
    const uint32_t smb = (uint32_t)__cvta_generic_to_shared(smem);
    float* ps  = (float*)(smem + OFF_PS);
    float* bsm = (float*)(smem + OFF_BSM);

    const int tid  = threadIdx.x;
    const int wid  = tid >> 5;
    const int lane = tid & 31;
    const int gq   = lane >> 2;
    const int tq   = lane & 3;
    uint32_t srank;
    asm("mov.u32 %0, %%cluster_ctarank;" : "=r"(srank));
    const int s = (int)srank;
    const int g = blockIdx.x >> 2;

    // ---- init: W1/W2 fragments -> SMEM ----
    {
        const int r0g = ((wid * 16 + gq) >> 6 << 8) + (s << 6) + ((wid * 16 + gq) & 63);
        const int r1g = ((wid * 16 + gq + 8) >> 6 << 8) + (s << 6) + ((wid * 16 + gq + 8) & 63);
        const float* W0 = Whh + (size_t)r0g * 256;
        const float* W1 = Whh + (size_t)r1g * 256;
#pragma unroll
        for (int kt = 0; kt < 16; ++kt) {
            int c0 = kt * 16 + tq * 2;
            float w00 = W0[c0],     w01 = W0[c0 + 1];
            float w10 = W1[c0],     w11 = W1[c0 + 1];
            float w02 = W0[c0 + 8], w03 = W0[c0 + 9];
            float w12 = W1[c0 + 8], w13 = W1[c0 + 9];
            uint4 w1v, w2v;
            w1v.x = pkbf(w00, w01); w1v.y = pkbf(w10, w11);
            w1v.z = pkbf(w02, w03); w1v.w = pkbf(w12, w13);
            w2v.x = pkbf(bfres(w00), bfres(w01));
            w2v.y = pkbf(bfres(w10), bfres(w11));
            w2v.z = pkbf(bfres(w02), bfres(w03));
            w2v.w = pkbf(bfres(w12), bfres(w13));
            uint32_t o = (uint32_t)(((wid * 16 + kt) * 32 + lane) * 16);
            *(uint4*)(smem + OFF_W1 + o) = w1v;
            *(uint4*)(smem + OFF_W2 + o) = w2v;
        }
    }
    if (tid < 192) {
        int grow = ((tid >> 6) << 8) + (s << 6) + (tid & 63);
        bsm[tid] = bhh[grow];
    }
    for (int i = tid; i < 16384 / 4; i += TPB2)
        ((float*)(smem + OFF_HSM))[i] = 0.f;
    if (tid == 0) {
        asm volatile("mbarrier.init.shared.b64 [%0], %1;"
                     :: "r"(smb + OFF_MBAR), "r"(4u) : "memory");
    }
    __syncthreads();
    asm volatile("barrier.cluster.arrive.aligned;" ::: "memory");
    asm volatile("barrier.cluster.wait.aligned;" ::: "memory");

    const int jj = tid >> 2;              // gate j (tid<256)
    const int bq = (tid & 3) * 2;         // gate batch pair
    const int kln = lane & 15;
    const uint32_t khalf = (uint32_t)(lane >> 4);

    float br = 0.f, bz = 0.f, bn_ = 0.f;
    if (tid < 256) { br = bsm[jj]; bz = bsm[64 + jj]; bn_ = bsm[128 + jj]; }

    const int pk = (s << 6) + jj;
    const uint32_t push_hi_off = (uint32_t)(OFF_HSM + pk * 32 + (((pk >> 2) & 1) << 4) + bq * 2);

    const char* w1p = smem + OFF_W1 + (size_t)wid * 8192 + lane * 16;
    const char* w2p = smem + OFF_W2 + (size_t)wid * 8192 + lane * 16;

    float2 ho = make_float2(0.f, 0.f);    // h_old in registers

    for (int t = 0; t < TT; ++t) {
        const int p = t & 1;

        // prefetch xg(t)
        float xr0, xz0, xn0, xr1, xz1, xn1;
        if (tid < 256) {
            size_t base = ((size_t)(g * 8 + bq) * TT + t) * GG + (s << 6) + jj;
            xr0 = g_xg[base];          xz0 = g_xg[base + 256];
            xn0 = g_xg[base + 512];
            xr1 = g_xg[base + (size_t)TT * GG];
            xz1 = g_xg[base + (size_t)TT * GG + 256];
            xn1 = g_xg[base + (size_t)TT * GG + 512];
        }

        // wait for step t-1 h-exchange (4 arrivals); parity (t-1)&1
        if (t) mbar_waitc(smb + OFF_MBAR, (uint32_t)((t - 1) & 1));

        // ---- GEMM: 16 kt, 6 independent accumulator chains ----
        float ch[6][4];
#pragma unroll
        for (int i = 0; i < 6; ++i)
#pragma unroll
            for (int q = 0; q < 4; ++q) ch[i][q] = 0.f;
        {
            const uint32_t hbase = smb + (uint32_t)(OFF_HSM + p * 8192);
#pragma unroll
            for (int kt = 0; kt < 16; ++kt) {
                uint4 w1 = *(const uint4*)(w1p + kt * 512);
                uint4 w2 = *(const uint4*)(w2p + kt * 512);
                int k0 = kt * 16 + kln;
                uint32_t addr = (hbase +
                    (uint32_t)(k0 * 32 + (((k0 >> 2) & 1) << 4))) ^ (khalf << 4);
                uint32_t b0, b1, b2, b3;     // b0,b1 = hi frags; b2,b3 = lo frags
                ldsm_x4t(b0, b1, b2, b3, addr);
                float* cA = ch[kt & 1];
                float* cB = ch[2 + (kt & 1)];
                float* cC = ch[4 + (kt & 1)];
                mma16816(cA[0], cA[1], cA[2], cA[3],
                         w1.x, w1.y, w1.z, w1.w, b0, b1);
                mma16816(cB[0], cB[1], cB[2], cB[3],
                         w1.x, w1.y, w1.z, w1.w, b2, b3);
                mma16816(cC[0], cC[1], cC[2], cC[3],
                         w2.x, w2.y, w2.z, w2.w, b0, b1);
            }
        }
        float c0 = (ch[0][0] + ch[1][0]) + (ch[2][0] + ch[3][0]) + (ch[4][0] + ch[5][0]);
        float c1 = (ch[0][1] + ch[1][1]) + (ch[2][1] + ch[3][1]) + (ch[4][1] + ch[5][1]);
        float c2 = (ch[0][2] + ch[1][2]) + (ch[2][2] + ch[3][2]) + (ch[4][2] + ch[5][2]);
        float c3 = (ch[0][3] + ch[1][3]) + (ch[2][3] + ch[3][3]) + (ch[4][3] + ch[5][3]);

        *(float2*)(ps + (wid * 16 + gq) * 8 + tq * 2)     = make_float2(c0, c1);
        *(float2*)(ps + (wid * 16 + gq + 8) * 8 + tq * 2) = make_float2(c2, c3);
        __syncthreads();

        // ---- gates: 256 threads x (1 j, 2 batches) ----
        if (tid < 256) {
            float2 hr = *(const float2*)(ps + jj * 8 + bq);
            float2 hz = *(const float2*)(ps + (64 + jj) * 8 + bq);
            float2 hn = *(const float2*)(ps + (128 + jj) * 8 + bq);

            float r0g = __fdividef(1.f, 1.f + __expf(-(xr0 + hr.x + br)));
            float z0g = __fdividef(1.f, 1.f + __expf(-(xz0 + hz.x + bz)));
            float v0  = xn0 + r0g * (hn.x + bn_);
            float n0  = 1.f - 2.f * __fdividef(1.f, __expf(2.f * v0) + 1.f);
            float hw0 = (1.f - z0g) * n0 + z0g * ho.x;

            float r1g = __fdividef(1.f, 1.f + __expf(-(xr1 + hr.y + br)));
            float z1g = __fdividef(1.f, 1.f + __expf(-(xz1 + hz.y + bz)));
            float v1  = xn1 + r1g * (hn.y + bn_);
            float n1  = 1.f - 2.f * __fdividef(1.f, __expf(2.f * v1) + 1.f);
            float hw1 = (1.f - z1g) * n1 + z1g * ho.y;

            uint32_t hiw = pkbf(hw0, hw1);
            uint32_t low = pkbf(bfres(hw0), bfres(hw1));

            uint32_t hiA = smb + push_hi_off + (uint32_t)((1 - p) * 8192);
            uint32_t loA = hiA ^ 16u;
#pragma unroll
            for (int rk = 0; rk < 4; ++rk) {
                uint32_t ra, rb;
                asm volatile("mapa.shared::cluster.u32 %0, %1, %2;"
                             : "=r"(ra) : "r"(hiA), "r"(rk));
                asm volatile("mapa.shared::cluster.u32 %0, %1, %2;"
                             : "=r"(rb) : "r"(loA), "r"(rk));
                asm volatile("st.shared::cluster.b32 [%0], %1;"
                             :: "r"(ra), "r"(hiw) : "memory");
                asm volatile("st.shared::cluster.b32 [%0], %1;"
                             :: "r"(rb), "r"(low) : "memory");
            }

            size_t ob = ((size_t)(g * 8 + bq) * TT + t) * HH + (s << 6) + jj;
            out[ob] = hw0;
            out[ob + (size_t)TT * HH] = hw1;
            ho = make_float2(hw0, hw1);
        }
        __syncthreads();

        // ---- signal all ranks: this CTA's pushes for step t are done ----
        if (tid == 0) {
            asm volatile("fence.acq_rel.cluster;" ::: "memory");
#pragma unroll
            for (int rk = 0; rk < 4; ++rk) {
                uint32_t ra;
                asm volatile("mapa.shared::cluster.u32 %0, %1, %2;"
                             : "=r"(ra) : "r"(smb + OFF_MBAR), "r"(rk));
                asm volatile("mbarrier.arrive.shared::cluster.b64 _, [%0];"
                             :: "r"(ra) : "memory");
            }
        }
    }

    // consume final phase, clean up
    mbar_waitc(smb + OFF_MBAR, (uint32_t)((TT - 1) & 1));
    __syncthreads();
    if (tid == 0) {
        asm volatile("mbarrier.inval.shared.b64 [%0];"
                     :: "r"(smb + OFF_MBAR) : "memory");
    }
    asm volatile("barrier.cluster.arrive.aligned;" ::: "memory");
    asm volatile("barrier.cluster.wait.aligned;" ::: "memory");
}

// ---------------------------------------------------------------------------
extern "C" void kernel_launch(void* const* d_in, const int* in_sizes, int n_in,
                              void* d_out, int out_size)
{
    const float* x   = (const float*)d_in[0];
    const float* Wih = (const float*)d_in[1];
    const float* Whh = (const float*)d_in[2];
    const float* bih = (const float*)d_in[3];
    const float* bhh = (const float*)d_in[4];
    float* out = (float*)d_out;

    cudaFuncSetAttribute(xg_mma_kernel,
                         cudaFuncAttributeMaxDynamicSharedMemorySize, SM1_BYTES);
    cudaFuncSetAttribute(gru_seq_mma,
                         cudaFuncAttributeMaxDynamicSharedMemorySize, SM2_BYTES);

    dim3 g1(GG / 64, BB * TT / 128);
    xg_mma_kernel<<<g1, 256, SM1_BYTES>>>(x, Wih, bih);
    gru_seq_mma<<<128, TPB2, SM2_BYTES>>>(Whh, bhh, out);
}